// round 6
// baseline (speedup 1.0000x reference)
#include <cuda_runtime.h>
#include <cstdint>

typedef unsigned long long ull;

// Problem constants (fixed shapes per reference)
#define NN    100000
#define EE    1600000
#define CINn  64
#define COUTn 128
#define SCAN_B 512

// ---------------- scratch (static device globals; no runtime alloc) ----------------
__device__ float g_agg0[(size_t)NN * CINn];
__device__ float g_agg1[(size_t)NN * COUTn];
__device__ float g_h0[(size_t)NN * COUTn];
__device__ float g_h1[(size_t)NN * COUTn];
__device__ float g_r[(size_t)NN * COUTn];
__device__ float g_stats[4 * COUTn];
__device__ float g_bnp[4 * COUTn];
// CSR scratch
__device__ int g_deg[NN];
__device__ int g_lscan[NN];
__device__ int g_part[256];
__device__ int g_rowptr[NN + 1];
__device__ int g_cursor[NN];
__device__ int g_eidx[EE];

// ---------------- packed fp32x2 FMA ----------------
#define FMA2(acc, a, w) \
    asm("fma.rn.f32x2 %0, %1, %2, %0;" : "+l"(acc) : "l"(a), "l"(w))

__device__ __forceinline__ ull dup2(float f) {
    ull r;
    asm("mov.b64 %0, {%1, %1};" : "=l"(r) : "f"(f));
    return r;
}

union F2 { ull u; float2 f; };
union W4 { float4 v; ull u[2]; };

// =============================================================================
// CSR build: histogram -> scan -> fill
// =============================================================================
__global__ void hist_kernel(const int* __restrict__ dst, int* __restrict__ deg, int E) {
    const int e = blockIdx.x * blockDim.x + threadIdx.x;
    if (e < E) atomicAdd(&deg[dst[e]], 1);
}

__global__ void scan1_kernel(const int* __restrict__ deg, int* __restrict__ lscan,
                             int* __restrict__ part, int N) {
    __shared__ int sh[SCAN_B];
    const int i = blockIdx.x * SCAN_B + threadIdx.x;
    const int v = (i < N) ? deg[i] : 0;
    sh[threadIdx.x] = v;
    __syncthreads();
#pragma unroll
    for (int off = 1; off < SCAN_B; off <<= 1) {
        int t = (threadIdx.x >= off) ? sh[threadIdx.x - off] : 0;
        __syncthreads();
        sh[threadIdx.x] += t;
        __syncthreads();
    }
    if (i < N) lscan[i] = sh[threadIdx.x] - v;
    if (threadIdx.x == SCAN_B - 1) part[blockIdx.x] = sh[threadIdx.x];
}

__global__ void scan2_kernel(int* __restrict__ part, int nb) {
    __shared__ int sh[256];
    const int v = (threadIdx.x < nb) ? part[threadIdx.x] : 0;
    sh[threadIdx.x] = v;
    __syncthreads();
#pragma unroll
    for (int off = 1; off < 256; off <<= 1) {
        int t = (threadIdx.x >= off) ? sh[threadIdx.x - off] : 0;
        __syncthreads();
        sh[threadIdx.x] += t;
        __syncthreads();
    }
    if (threadIdx.x < nb) part[threadIdx.x] = sh[threadIdx.x] - v;
}

__global__ void scan3_kernel(const int* __restrict__ lscan, const int* __restrict__ part,
                             int* __restrict__ rowptr, int* __restrict__ cursor,
                             int N, int E) {
    const int i = blockIdx.x * blockDim.x + threadIdx.x;
    if (i < N) {
        const int r = lscan[i] + part[i / SCAN_B];
        rowptr[i] = r;
        cursor[i] = r;
    }
    if (i == 0) rowptr[N] = E;
}

__global__ void fill_kernel(const int* __restrict__ src, const int* __restrict__ dst,
                            int* __restrict__ cursor, int* __restrict__ eidx, int E) {
    const int e = blockIdx.x * blockDim.x + threadIdx.x;
    if (e < E) {
        const int pos = atomicAdd(&cursor[dst[e]], 1);
        eidx[pos] = src[e];
    }
}

// =============================================================================
// Gather (layer 0): agg0[n] = sum x[src], 4-edge unrolled, C4=16
// =============================================================================
__global__ void gather0_kernel(const int* __restrict__ rowptr, const int* __restrict__ eidx,
                               const float4* __restrict__ feat, float4* __restrict__ agg,
                               int N) {
    const int g = threadIdx.x >> 4;
    const int c = threadIdx.x & 15;
    const int node = blockIdx.x * 16 + g;
    if (node >= N) return;
    const int beg = rowptr[node];
    const int end = rowptr[node + 1];
    float4 acc = make_float4(0.f, 0.f, 0.f, 0.f);
    int e = beg;
    for (; e + 3 < end; e += 4) {
        const int s0 = eidx[e], s1 = eidx[e + 1], s2 = eidx[e + 2], s3 = eidx[e + 3];
        const float4 v0 = feat[(size_t)s0 * 16 + c];
        const float4 v1 = feat[(size_t)s1 * 16 + c];
        const float4 v2 = feat[(size_t)s2 * 16 + c];
        const float4 v3 = feat[(size_t)s3 * 16 + c];
        acc.x += v0.x + v1.x + v2.x + v3.x;
        acc.y += v0.y + v1.y + v2.y + v3.y;
        acc.z += v0.z + v1.z + v2.z + v3.z;
        acc.w += v0.w + v1.w + v2.w + v3.w;
    }
    for (; e < end; e++) {
        const int s = eidx[e];
        const float4 v = feat[(size_t)s * 16 + c];
        acc.x += v.x; acc.y += v.y; acc.z += v.z; acc.w += v.w;
    }
    agg[(size_t)node * 16 + c] = acc;
}

// =============================================================================
// Gather (layer 1) with fused bn+relu: agg1[n] = sum relu(bn(h0[src])), C4=32
// =============================================================================
__global__ void gather1_kernel(const int* __restrict__ rowptr, const int* __restrict__ eidx,
                               const float4* __restrict__ h0, const float* __restrict__ bnp,
                               float4* __restrict__ agg, int N) {
    const int g = threadIdx.x >> 5;
    const int c = threadIdx.x & 31;
    const int node = blockIdx.x * 8 + g;
    if (node >= N) return;
    const float sc0 = bnp[c * 4 + 0], sh0 = bnp[128 + c * 4 + 0];
    const float sc1 = bnp[c * 4 + 1], sh1 = bnp[128 + c * 4 + 1];
    const float sc2 = bnp[c * 4 + 2], sh2 = bnp[128 + c * 4 + 2];
    const float sc3 = bnp[c * 4 + 3], sh3 = bnp[128 + c * 4 + 3];
    const int beg = rowptr[node];
    const int end = rowptr[node + 1];
    float4 acc = make_float4(0.f, 0.f, 0.f, 0.f);
    int e = beg;
    for (; e + 3 < end; e += 4) {
        const int s0 = eidx[e], s1 = eidx[e + 1], s2 = eidx[e + 2], s3 = eidx[e + 3];
        const float4 v0 = h0[(size_t)s0 * 32 + c];
        const float4 v1 = h0[(size_t)s1 * 32 + c];
        const float4 v2 = h0[(size_t)s2 * 32 + c];
        const float4 v3 = h0[(size_t)s3 * 32 + c];
        acc.x += fmaxf(fmaf(v0.x, sc0, sh0), 0.f) + fmaxf(fmaf(v1.x, sc0, sh0), 0.f)
               + fmaxf(fmaf(v2.x, sc0, sh0), 0.f) + fmaxf(fmaf(v3.x, sc0, sh0), 0.f);
        acc.y += fmaxf(fmaf(v0.y, sc1, sh1), 0.f) + fmaxf(fmaf(v1.y, sc1, sh1), 0.f)
               + fmaxf(fmaf(v2.y, sc1, sh1), 0.f) + fmaxf(fmaf(v3.y, sc1, sh1), 0.f);
        acc.z += fmaxf(fmaf(v0.z, sc2, sh2), 0.f) + fmaxf(fmaf(v1.z, sc2, sh2), 0.f)
               + fmaxf(fmaf(v2.z, sc2, sh2), 0.f) + fmaxf(fmaf(v3.z, sc2, sh2), 0.f);
        acc.w += fmaxf(fmaf(v0.w, sc3, sh3), 0.f) + fmaxf(fmaf(v1.w, sc3, sh3), 0.f)
               + fmaxf(fmaf(v2.w, sc3, sh3), 0.f) + fmaxf(fmaf(v3.w, sc3, sh3), 0.f);
    }
    for (; e < end; e++) {
        const int s = eidx[e];
        const float4 v = h0[(size_t)s * 32 + c];
        acc.x += fmaxf(fmaf(v.x, sc0, sh0), 0.f);
        acc.y += fmaxf(fmaf(v.y, sc1, sh1), 0.f);
        acc.z += fmaxf(fmaf(v.z, sc2, sh2), 0.f);
        acc.w += fmaxf(fmaf(v.w, sc3, sh3), 0.f);
    }
    agg[(size_t)node * 32 + c] = acc;
}

// =============================================================================
// Merged layer-0 GEMM: r = x@Wlin^T + blin ; h0 = x@Wr0^T + agg0@Wn0^T + b0.
// Shares x staging between r and h0. BM=64, BN=128, BK=16, K=64.
// Fuses per-column BN stats of h0.
// =============================================================================
__global__ __launch_bounds__(256) void gemm0_kernel(
    const float* __restrict__ x, const float* __restrict__ agg0,
    const float* __restrict__ Wr0, const float* __restrict__ Wlin,
    const float* __restrict__ Wn0,
    const float* __restrict__ blin, const float* __restrict__ b0,
    float* __restrict__ r, float* __restrict__ h0,
    float* __restrict__ stats, int Nn) {

    __shared__ alignas(16) ull As2[16 * 66];
    __shared__ alignas(16) float WsA[16][128];   // Wr0 (pass0) / Wn0 (pass1)
    __shared__ alignas(16) float WsB[16][128];   // Wlin (pass0)
    __shared__ float sh_sum[128];
    __shared__ float sh_sq[128];

    const int tid  = threadIdx.x;
    const int row0 = blockIdx.x * 64;
    const int warp = tid >> 5;
    const int lane = tid & 31;
    const int tm   = warp * 8;
    const int tn   = lane * 4;

    if (tid < 128) { sh_sum[tid] = 0.f; sh_sq[tid] = 0.f; }

    ull acch[8][2], accr[8][2];
#pragma unroll
    for (int i = 0; i < 8; i++) {
        acch[i][0] = 0ull; acch[i][1] = 0ull;
        accr[i][0] = 0ull; accr[i][1] = 0ull;
    }

    // ---- pass 0: A = x, weights = Wr0 (->h0) and Wlin (->r) ----
    for (int k0 = 0; k0 < 64; k0 += 16) {
        {
            const int m  = tid >> 2;
            const int kq = (tid & 3) * 4;
            const int rr = row0 + m;
            float4 v = make_float4(0.f, 0.f, 0.f, 0.f);
            if (rr < Nn) v = *(const float4*)(x + (size_t)rr * 64 + k0 + kq);
            As2[(kq + 0) * 66 + m] = dup2(v.x);
            As2[(kq + 1) * 66 + m] = dup2(v.y);
            As2[(kq + 2) * 66 + m] = dup2(v.z);
            As2[(kq + 3) * 66 + m] = dup2(v.w);
        }
        {
            const int n  = tid >> 1;
            const int kq = (tid & 1) * 8;
            const float* wa = Wr0 + (size_t)n * 64 + k0 + kq;
            const float* wb = Wlin + (size_t)n * 64 + k0 + kq;
            float4 a0 = *(const float4*)(wa);
            float4 a1 = *(const float4*)(wa + 4);
            float4 b0v = *(const float4*)(wb);
            float4 b1v = *(const float4*)(wb + 4);
            WsA[kq + 0][n] = a0.x; WsA[kq + 1][n] = a0.y;
            WsA[kq + 2][n] = a0.z; WsA[kq + 3][n] = a0.w;
            WsA[kq + 4][n] = a1.x; WsA[kq + 5][n] = a1.y;
            WsA[kq + 6][n] = a1.z; WsA[kq + 7][n] = a1.w;
            WsB[kq + 0][n] = b0v.x; WsB[kq + 1][n] = b0v.y;
            WsB[kq + 2][n] = b0v.z; WsB[kq + 3][n] = b0v.w;
            WsB[kq + 4][n] = b1v.x; WsB[kq + 5][n] = b1v.y;
            WsB[kq + 6][n] = b1v.z; WsB[kq + 7][n] = b1v.w;
        }
        __syncthreads();
#pragma unroll
        for (int kk = 0; kk < 16; kk++) {
            const ulonglong2* ap = (const ulonglong2*)&As2[kk * 66 + tm];
            const ulonglong2 a01 = ap[0];
            const ulonglong2 a23 = ap[1];
            const ulonglong2 a45 = ap[2];
            const ulonglong2 a67 = ap[3];
            W4 wa, wb;
            wa.v = *(const float4*)&WsA[kk][tn];
            wb.v = *(const float4*)&WsB[kk][tn];
            FMA2(acch[0][0], a01.x, wa.u[0]); FMA2(acch[0][1], a01.x, wa.u[1]);
            FMA2(acch[1][0], a01.y, wa.u[0]); FMA2(acch[1][1], a01.y, wa.u[1]);
            FMA2(acch[2][0], a23.x, wa.u[0]); FMA2(acch[2][1], a23.x, wa.u[1]);
            FMA2(acch[3][0], a23.y, wa.u[0]); FMA2(acch[3][1], a23.y, wa.u[1]);
            FMA2(acch[4][0], a45.x, wa.u[0]); FMA2(acch[4][1], a45.x, wa.u[1]);
            FMA2(acch[5][0], a45.y, wa.u[0]); FMA2(acch[5][1], a45.y, wa.u[1]);
            FMA2(acch[6][0], a67.x, wa.u[0]); FMA2(acch[6][1], a67.x, wa.u[1]);
            FMA2(acch[7][0], a67.y, wa.u[0]); FMA2(acch[7][1], a67.y, wa.u[1]);
            FMA2(accr[0][0], a01.x, wb.u[0]); FMA2(accr[0][1], a01.x, wb.u[1]);
            FMA2(accr[1][0], a01.y, wb.u[0]); FMA2(accr[1][1], a01.y, wb.u[1]);
            FMA2(accr[2][0], a23.x, wb.u[0]); FMA2(accr[2][1], a23.x, wb.u[1]);
            FMA2(accr[3][0], a23.y, wb.u[0]); FMA2(accr[3][1], a23.y, wb.u[1]);
            FMA2(accr[4][0], a45.x, wb.u[0]); FMA2(accr[4][1], a45.x, wb.u[1]);
            FMA2(accr[5][0], a45.y, wb.u[0]); FMA2(accr[5][1], a45.y, wb.u[1]);
            FMA2(accr[6][0], a67.x, wb.u[0]); FMA2(accr[6][1], a67.x, wb.u[1]);
            FMA2(accr[7][0], a67.y, wb.u[0]); FMA2(accr[7][1], a67.y, wb.u[1]);
        }
        __syncthreads();
    }

    // ---- pass 1: A = agg0, weight = Wn0 (->h0) ----
    for (int k0 = 0; k0 < 64; k0 += 16) {
        {
            const int m  = tid >> 2;
            const int kq = (tid & 3) * 4;
            const int rr = row0 + m;
            float4 v = make_float4(0.f, 0.f, 0.f, 0.f);
            if (rr < Nn) v = *(const float4*)(agg0 + (size_t)rr * 64 + k0 + kq);
            As2[(kq + 0) * 66 + m] = dup2(v.x);
            As2[(kq + 1) * 66 + m] = dup2(v.y);
            As2[(kq + 2) * 66 + m] = dup2(v.z);
            As2[(kq + 3) * 66 + m] = dup2(v.w);
        }
        {
            const int n  = tid >> 1;
            const int kq = (tid & 1) * 8;
            const float* wa = Wn0 + (size_t)n * 64 + k0 + kq;
            float4 a0 = *(const float4*)(wa);
            float4 a1 = *(const float4*)(wa + 4);
            WsA[kq + 0][n] = a0.x; WsA[kq + 1][n] = a0.y;
            WsA[kq + 2][n] = a0.z; WsA[kq + 3][n] = a0.w;
            WsA[kq + 4][n] = a1.x; WsA[kq + 5][n] = a1.y;
            WsA[kq + 6][n] = a1.z; WsA[kq + 7][n] = a1.w;
        }
        __syncthreads();
#pragma unroll
        for (int kk = 0; kk < 16; kk++) {
            const ulonglong2* ap = (const ulonglong2*)&As2[kk * 66 + tm];
            const ulonglong2 a01 = ap[0];
            const ulonglong2 a23 = ap[1];
            const ulonglong2 a45 = ap[2];
            const ulonglong2 a67 = ap[3];
            W4 wa;
            wa.v = *(const float4*)&WsA[kk][tn];
            FMA2(acch[0][0], a01.x, wa.u[0]); FMA2(acch[0][1], a01.x, wa.u[1]);
            FMA2(acch[1][0], a01.y, wa.u[0]); FMA2(acch[1][1], a01.y, wa.u[1]);
            FMA2(acch[2][0], a23.x, wa.u[0]); FMA2(acch[2][1], a23.x, wa.u[1]);
            FMA2(acch[3][0], a23.y, wa.u[0]); FMA2(acch[3][1], a23.y, wa.u[1]);
            FMA2(acch[4][0], a45.x, wa.u[0]); FMA2(acch[4][1], a45.x, wa.u[1]);
            FMA2(acch[5][0], a45.y, wa.u[0]); FMA2(acch[5][1], a45.y, wa.u[1]);
            FMA2(acch[6][0], a67.x, wa.u[0]); FMA2(acch[6][1], a67.x, wa.u[1]);
            FMA2(acch[7][0], a67.y, wa.u[0]); FMA2(acch[7][1], a67.y, wa.u[1]);
        }
        __syncthreads();
    }

    // ---- epilogue ----
    const float bl0 = __ldg(blin + tn), bl1 = __ldg(blin + tn + 1);
    const float bl2 = __ldg(blin + tn + 2), bl3 = __ldg(blin + tn + 3);
    const float bh0 = __ldg(b0 + tn), bh1 = __ldg(b0 + tn + 1);
    const float bh2 = __ldg(b0 + tn + 2), bh3 = __ldg(b0 + tn + 3);
    float psum[4] = {0.f, 0.f, 0.f, 0.f};
    float psq[4]  = {0.f, 0.f, 0.f, 0.f};
#pragma unroll
    for (int i = 0; i < 8; i++) {
        const int rr = row0 + tm + i;
        if (rr < Nn) {
            F2 p0, p1;
            p0.u = accr[i][0]; p1.u = accr[i][1];
            float4 orv;
            orv.x = p0.f.x + bl0; orv.y = p0.f.y + bl1;
            orv.z = p1.f.x + bl2; orv.w = p1.f.y + bl3;
            *(float4*)(r + (size_t)rr * 128 + tn) = orv;
            p0.u = acch[i][0]; p1.u = acch[i][1];
            float4 o;
            o.x = p0.f.x + bh0; o.y = p0.f.y + bh1;
            o.z = p1.f.x + bh2; o.w = p1.f.y + bh3;
            *(float4*)(h0 + (size_t)rr * 128 + tn) = o;
            psum[0] += o.x; psum[1] += o.y; psum[2] += o.z; psum[3] += o.w;
            psq[0] += o.x * o.x; psq[1] += o.y * o.y;
            psq[2] += o.z * o.z; psq[3] += o.w * o.w;
        }
    }
#pragma unroll
    for (int j = 0; j < 4; j++) {
        atomicAdd(&sh_sum[tn + j], psum[j]);
        atomicAdd(&sh_sq[tn + j], psq[j]);
    }
    __syncthreads();
    if (tid < 128) {
        atomicAdd(&stats[tid], sh_sum[tid]);
        atomicAdd(&stats[128 + tid], sh_sq[tid]);
    }
}

// =============================================================================
// Layer-1 GEMM: h1 = relu(bn0(h0))@Wr1^T + agg1@Wn1^T + b1 (+ BN stats).
// BM=64, BN=128, BK=32, K=128. Pass 0 applies bn+relu during A staging.
// =============================================================================
__global__ __launch_bounds__(256) void gemm1_kernel(
    const float* __restrict__ h0, const float* __restrict__ Wr1,
    const float* __restrict__ agg1, const float* __restrict__ Wn1,
    const float* __restrict__ bnp, const float* __restrict__ bias,
    float* __restrict__ C, float* __restrict__ stats, int Nn) {

    __shared__ alignas(16) ull As2[32 * 66];
    __shared__ alignas(16) float Ws[32][128];
    __shared__ float sbn[256];
    __shared__ float sh_sum[128];
    __shared__ float sh_sq[128];

    const int tid  = threadIdx.x;
    const int row0 = blockIdx.x * 64;
    const int warp = tid >> 5;
    const int lane = tid & 31;
    const int tm   = warp * 8;
    const int tn   = lane * 4;

    if (tid < 128) { sh_sum[tid] = 0.f; sh_sq[tid] = 0.f; }
    sbn[tid] = bnp[tid];   // 256 threads load scale[0:128] | shift[0:128]

    ull acc2[8][2];
#pragma unroll
    for (int i = 0; i < 8; i++) { acc2[i][0] = 0ull; acc2[i][1] = 0ull; }

    for (int mat = 0; mat < 2; mat++) {
        const float* Ap = mat ? agg1 : h0;
        const float* Wp = mat ? Wn1 : Wr1;
        for (int k0 = 0; k0 < 128; k0 += 32) {
            if (mat == 0 && k0 == 0) __syncthreads();  // sbn visible (also first tile)
            // A tile: 64 rows x 32 k (2 float4 per thread)
#pragma unroll
            for (int p = 0; p < 2; p++) {
                const int idx = tid + p * 256;
                const int m  = idx >> 3;
                const int kq = (idx & 7) * 4;
                const int rr = row0 + m;
                float4 v = make_float4(0.f, 0.f, 0.f, 0.f);
                if (rr < Nn) v = *(const float4*)(Ap + (size_t)rr * 128 + k0 + kq);
                if (mat == 0) {
                    const int cc = k0 + kq;
                    v.x = fmaxf(fmaf(v.x, sbn[cc + 0], sbn[128 + cc + 0]), 0.f);
                    v.y = fmaxf(fmaf(v.y, sbn[cc + 1], sbn[128 + cc + 1]), 0.f);
                    v.z = fmaxf(fmaf(v.z, sbn[cc + 2], sbn[128 + cc + 2]), 0.f);
                    v.w = fmaxf(fmaf(v.w, sbn[cc + 3], sbn[128 + cc + 3]), 0.f);
                }
                As2[(kq + 0) * 66 + m] = dup2(v.x);
                As2[(kq + 1) * 66 + m] = dup2(v.y);
                As2[(kq + 2) * 66 + m] = dup2(v.z);
                As2[(kq + 3) * 66 + m] = dup2(v.w);
            }
            // W tile: 128 n x 32 k (4 float4 per thread)
#pragma unroll
            for (int p = 0; p < 4; p++) {
                const int idx = tid + p * 256;
                const int n  = idx >> 3;
                const int kq = (idx & 7) * 4;
                const float4 v = *(const float4*)(Wp + (size_t)n * 128 + k0 + kq);
                Ws[kq + 0][n] = v.x; Ws[kq + 1][n] = v.y;
                Ws[kq + 2][n] = v.z; Ws[kq + 3][n] = v.w;
            }
            __syncthreads();
#pragma unroll
            for (int kk = 0; kk < 32; kk++) {
                const ulonglong2* ap = (const ulonglong2*)&As2[kk * 66 + tm];
                const ulonglong2 a01 = ap[0];
                const ulonglong2 a23 = ap[1];
                const ulonglong2 a45 = ap[2];
                const ulonglong2 a67 = ap[3];
                W4 w;
                w.v = *(const float4*)&Ws[kk][tn];
                FMA2(acc2[0][0], a01.x, w.u[0]); FMA2(acc2[0][1], a01.x, w.u[1]);
                FMA2(acc2[1][0], a01.y, w.u[0]); FMA2(acc2[1][1], a01.y, w.u[1]);
                FMA2(acc2[2][0], a23.x, w.u[0]); FMA2(acc2[2][1], a23.x, w.u[1]);
                FMA2(acc2[3][0], a23.y, w.u[0]); FMA2(acc2[3][1], a23.y, w.u[1]);
                FMA2(acc2[4][0], a45.x, w.u[0]); FMA2(acc2[4][1], a45.x, w.u[1]);
                FMA2(acc2[5][0], a45.y, w.u[0]); FMA2(acc2[5][1], a45.y, w.u[1]);
                FMA2(acc2[6][0], a67.x, w.u[0]); FMA2(acc2[6][1], a67.x, w.u[1]);
                FMA2(acc2[7][0], a67.y, w.u[0]); FMA2(acc2[7][1], a67.y, w.u[1]);
            }
            __syncthreads();
        }
    }

    // ---- epilogue ----
    const float bb0 = __ldg(bias + tn), bb1 = __ldg(bias + tn + 1);
    const float bb2 = __ldg(bias + tn + 2), bb3 = __ldg(bias + tn + 3);
    float psum[4] = {0.f, 0.f, 0.f, 0.f};
    float psq[4]  = {0.f, 0.f, 0.f, 0.f};
#pragma unroll
    for (int i = 0; i < 8; i++) {
        const int rr = row0 + tm + i;
        if (rr < Nn) {
            F2 p0, p1;
            p0.u = acc2[i][0]; p1.u = acc2[i][1];
            float4 o;
            o.x = p0.f.x + bb0; o.y = p0.f.y + bb1;
            o.z = p1.f.x + bb2; o.w = p1.f.y + bb3;
            *(float4*)(C + (size_t)rr * 128 + tn) = o;
            psum[0] += o.x; psum[1] += o.y; psum[2] += o.z; psum[3] += o.w;
            psq[0] += o.x * o.x; psq[1] += o.y * o.y;
            psq[2] += o.z * o.z; psq[3] += o.w * o.w;
        }
    }
#pragma unroll
    for (int j = 0; j < 4; j++) {
        atomicAdd(&sh_sum[tn + j], psum[j]);
        atomicAdd(&sh_sq[tn + j], psq[j]);
    }
    __syncthreads();
    if (tid < 128) {
        atomicAdd(&stats[tid], sh_sum[tid]);
        atomicAdd(&stats[128 + tid], sh_sq[tid]);
    }
}

// ---------------- BN finalize ----------------
__global__ void finalize_kernel(const float* __restrict__ stats,
                                const float* __restrict__ gamma,
                                const float* __restrict__ beta,
                                float* __restrict__ bnp, float invN) {
    const int c = threadIdx.x;
    const float mu   = stats[c] * invN;
    const float var  = stats[128 + c] * invN - mu * mu;
    const float rstd = rsqrtf(var + 1e-5f);
    const float sc   = rstd * gamma[c];
    bnp[c]       = sc;
    bnp[128 + c] = beta[c] - mu * sc;
}

// ---------------- out = relu(h1*scale + shift + r) ----------------
__global__ void final_kernel(const float4* __restrict__ h1, const float* __restrict__ bnp,
                             const float4* __restrict__ r, float4* __restrict__ out,
                             int total4) {
    const int i = blockIdx.x * blockDim.x + threadIdx.x;
    if (i >= total4) return;
    const int c = (i & 31) * 4;
    const float4 v = h1[i];
    const float4 rv = r[i];
    float4 o;
    o.x = fmaxf(fmaf(v.x, bnp[c + 0], bnp[128 + c + 0]) + rv.x, 0.f);
    o.y = fmaxf(fmaf(v.y, bnp[c + 1], bnp[128 + c + 1]) + rv.y, 0.f);
    o.z = fmaxf(fmaf(v.z, bnp[c + 2], bnp[128 + c + 2]) + rv.z, 0.f);
    o.w = fmaxf(fmaf(v.w, bnp[c + 3], bnp[128 + c + 3]) + rv.w, 0.f);
    out[i] = o;
}

// ---------------- launch ----------------
extern "C" void kernel_launch(void* const* d_in, const int* in_sizes, int n_in,
                              void* d_out, int out_size) {
    const float* x    = (const float*)d_in[0];
    const int*   ei   = (const int*)d_in[1];
    const float* Wr0  = (const float*)d_in[2];
    const float* Wn0  = (const float*)d_in[3];
    const float* b0   = (const float*)d_in[4];
    const float* g0   = (const float*)d_in[5];
    const float* be0  = (const float*)d_in[6];
    const float* Wr1  = (const float*)d_in[7];
    const float* Wn1  = (const float*)d_in[8];
    const float* b1   = (const float*)d_in[9];
    const float* g1   = (const float*)d_in[10];
    const float* be1  = (const float*)d_in[11];
    const float* Wlin = (const float*)d_in[12];
    const float* blin = (const float*)d_in[13];
    float* out = (float*)d_out;

    const int N = in_sizes[0] / CINn;
    const int E = in_sizes[1] / 2;
    const int* src = ei;
    const int* dst = ei + E;

    float *agg0, *agg1, *h0, *h1, *r, *stats, *bnp;
    int *deg, *lscan, *part, *rowptr, *cursor, *eidx;
    cudaGetSymbolAddress((void**)&agg0,   g_agg0);
    cudaGetSymbolAddress((void**)&agg1,   g_agg1);
    cudaGetSymbolAddress((void**)&h0,     g_h0);
    cudaGetSymbolAddress((void**)&h1,     g_h1);
    cudaGetSymbolAddress((void**)&r,      g_r);
    cudaGetSymbolAddress((void**)&stats,  g_stats);
    cudaGetSymbolAddress((void**)&bnp,    g_bnp);
    cudaGetSymbolAddress((void**)&deg,    g_deg);
    cudaGetSymbolAddress((void**)&lscan,  g_lscan);
    cudaGetSymbolAddress((void**)&part,   g_part);
    cudaGetSymbolAddress((void**)&rowptr, g_rowptr);
    cudaGetSymbolAddress((void**)&cursor, g_cursor);
    cudaGetSymbolAddress((void**)&eidx,   g_eidx);

    cudaMemsetAsync(deg,   0, (size_t)N * sizeof(int));
    cudaMemsetAsync(stats, 0, 4 * COUTn * sizeof(float));

    const int nb = (N + SCAN_B - 1) / SCAN_B;

    // ---- CSR build (once; reused by both layers) ----
    hist_kernel<<<(E + 255) / 256, 256>>>(dst, deg, E);
    scan1_kernel<<<nb, SCAN_B>>>(deg, lscan, part, N);
    scan2_kernel<<<1, 256>>>(part, nb);
    scan3_kernel<<<(N + 255) / 256, 256>>>(lscan, part, rowptr, cursor, N, E);
    fill_kernel<<<(E + 255) / 256, 256>>>(src, dst, cursor, eidx, E);

    const int gemmBlocks = (N + 63) / 64;
    const int T4 = N * 32;

    // ---- Layer 0 ----
    gather0_kernel<<<(N + 15) / 16, 256>>>(rowptr, eidx, (const float4*)x,
                                           (float4*)agg0, N);
    // r = x@Wlin^T + blin ; h0 = x@Wr0^T + agg0@Wn0^T + b0 (merged, fused stats)
    gemm0_kernel<<<gemmBlocks, 256>>>(x, agg0, Wr0, Wlin, Wn0, blin, b0, r, h0, stats, N);
    finalize_kernel<<<1, 128>>>(stats, g0, be0, bnp, 1.0f / (float)N);

    // ---- Layer 1 (y never materialized: bn+relu fused into consumers) ----
    gather1_kernel<<<(N + 7) / 8, 256>>>(rowptr, eidx, (const float4*)h0, bnp,
                                         (float4*)agg1, N);
    gemm1_kernel<<<gemmBlocks, 256>>>(h0, Wr1, agg1, Wn1, bnp, b1, h1,
                                      stats + 2 * COUTn, N);
    finalize_kernel<<<1, 128>>>(stats + 2 * COUTn, g1, be1, bnp + 2 * COUTn, 1.0f / (float)N);
    final_kernel<<<(T4 + 255) / 256, 256>>>((const float4*)h1, bnp + 2 * COUTn,
                                            (const float4*)r, (float4*)out, T4);
}

// round 7
// speedup vs baseline: 1.0491x; 1.0491x over previous
#include <cuda_runtime.h>
#include <cstdint>

typedef unsigned long long ull;

// Problem constants (fixed shapes per reference)
#define NN    100000
#define EE    1600000
#define CINn  64
#define COUTn 128
#define SCAN_B 512

// ---------------- scratch (static device globals; no runtime alloc) ----------------
__device__ float g_agg0[(size_t)NN * CINn];
__device__ float g_agg1[(size_t)NN * COUTn];
__device__ float g_h0[(size_t)NN * COUTn];
__device__ float g_h1[(size_t)NN * COUTn];
__device__ float g_r[(size_t)NN * COUTn];
__device__ float g_stats[4 * COUTn];
__device__ float g_bnp[4 * COUTn];
// CSR scratch
__device__ int g_deg[NN];
__device__ int g_lscan[NN];
__device__ int g_part[256];
__device__ int g_rowptr[NN + 1];
__device__ int g_cursor[NN];
__device__ int g_eidx[EE];

// ---------------- packed fp32x2 FMA ----------------
#define FMA2(acc, a, w) \
    asm("fma.rn.f32x2 %0, %1, %2, %0;" : "+l"(acc) : "l"(a), "l"(w))

__device__ __forceinline__ ull dup2(float f) {
    ull r;
    asm("mov.b64 %0, {%1, %1};" : "=l"(r) : "f"(f));
    return r;
}

union F2 { ull u; float2 f; };
union W4 { float4 v; ull u[2]; };

// =============================================================================
// CSR build: histogram -> scan -> fill
// =============================================================================
__global__ void hist_kernel(const int* __restrict__ dst, int* __restrict__ deg, int E) {
    const int e = blockIdx.x * blockDim.x + threadIdx.x;
    if (e < E) atomicAdd(&deg[dst[e]], 1);
}

__global__ void scan1_kernel(const int* __restrict__ deg, int* __restrict__ lscan,
                             int* __restrict__ part, int N) {
    __shared__ int sh[SCAN_B];
    const int i = blockIdx.x * SCAN_B + threadIdx.x;
    const int v = (i < N) ? deg[i] : 0;
    sh[threadIdx.x] = v;
    __syncthreads();
#pragma unroll
    for (int off = 1; off < SCAN_B; off <<= 1) {
        int t = (threadIdx.x >= off) ? sh[threadIdx.x - off] : 0;
        __syncthreads();
        sh[threadIdx.x] += t;
        __syncthreads();
    }
    if (i < N) lscan[i] = sh[threadIdx.x] - v;
    if (threadIdx.x == SCAN_B - 1) part[blockIdx.x] = sh[threadIdx.x];
}

__global__ void scan2_kernel(int* __restrict__ part, int nb) {
    __shared__ int sh[256];
    const int v = (threadIdx.x < nb) ? part[threadIdx.x] : 0;
    sh[threadIdx.x] = v;
    __syncthreads();
#pragma unroll
    for (int off = 1; off < 256; off <<= 1) {
        int t = (threadIdx.x >= off) ? sh[threadIdx.x - off] : 0;
        __syncthreads();
        sh[threadIdx.x] += t;
        __syncthreads();
    }
    if (threadIdx.x < nb) part[threadIdx.x] = sh[threadIdx.x] - v;
}

__global__ void scan3_kernel(const int* __restrict__ lscan, const int* __restrict__ part,
                             int* __restrict__ rowptr, int* __restrict__ cursor,
                             int N, int E) {
    const int i = blockIdx.x * blockDim.x + threadIdx.x;
    if (i < N) {
        const int r = lscan[i] + part[i / SCAN_B];
        rowptr[i] = r;
        cursor[i] = r;
    }
    if (i == 0) rowptr[N] = E;
}

__global__ void fill_kernel(const int* __restrict__ src, const int* __restrict__ dst,
                            int* __restrict__ cursor, int* __restrict__ eidx, int E) {
    const int e = blockIdx.x * blockDim.x + threadIdx.x;
    if (e < E) {
        const int pos = atomicAdd(&cursor[dst[e]], 1);
        eidx[pos] = src[e];
    }
}

// =============================================================================
// Gather (layer 0): agg0[n] = sum x[src], 4-edge unrolled, C4=16
// =============================================================================
__global__ void gather0_kernel(const int* __restrict__ rowptr, const int* __restrict__ eidx,
                               const float4* __restrict__ feat, float4* __restrict__ agg,
                               int N) {
    const int g = threadIdx.x >> 4;
    const int c = threadIdx.x & 15;
    const int node = blockIdx.x * 16 + g;
    if (node >= N) return;
    const int beg = rowptr[node];
    const int end = rowptr[node + 1];
    float4 acc = make_float4(0.f, 0.f, 0.f, 0.f);
    int e = beg;
    for (; e + 3 < end; e += 4) {
        const int s0 = eidx[e], s1 = eidx[e + 1], s2 = eidx[e + 2], s3 = eidx[e + 3];
        const float4 v0 = feat[(size_t)s0 * 16 + c];
        const float4 v1 = feat[(size_t)s1 * 16 + c];
        const float4 v2 = feat[(size_t)s2 * 16 + c];
        const float4 v3 = feat[(size_t)s3 * 16 + c];
        acc.x += v0.x + v1.x + v2.x + v3.x;
        acc.y += v0.y + v1.y + v2.y + v3.y;
        acc.z += v0.z + v1.z + v2.z + v3.z;
        acc.w += v0.w + v1.w + v2.w + v3.w;
    }
    for (; e < end; e++) {
        const int s = eidx[e];
        const float4 v = feat[(size_t)s * 16 + c];
        acc.x += v.x; acc.y += v.y; acc.z += v.z; acc.w += v.w;
    }
    agg[(size_t)node * 16 + c] = acc;
}

// =============================================================================
// Gather (layer 1) with fused bn+relu: agg1[n] = sum relu(bn(h0[src])), C4=32
// =============================================================================
__global__ void gather1_kernel(const int* __restrict__ rowptr, const int* __restrict__ eidx,
                               const float4* __restrict__ h0, const float* __restrict__ bnp,
                               float4* __restrict__ agg, int N) {
    const int g = threadIdx.x >> 5;
    const int c = threadIdx.x & 31;
    const int node = blockIdx.x * 8 + g;
    if (node >= N) return;
    const float sc0 = bnp[c * 4 + 0], sh0 = bnp[128 + c * 4 + 0];
    const float sc1 = bnp[c * 4 + 1], sh1 = bnp[128 + c * 4 + 1];
    const float sc2 = bnp[c * 4 + 2], sh2 = bnp[128 + c * 4 + 2];
    const float sc3 = bnp[c * 4 + 3], sh3 = bnp[128 + c * 4 + 3];
    const int beg = rowptr[node];
    const int end = rowptr[node + 1];
    float4 acc = make_float4(0.f, 0.f, 0.f, 0.f);
    int e = beg;
    for (; e + 3 < end; e += 4) {
        const int s0 = eidx[e], s1 = eidx[e + 1], s2 = eidx[e + 2], s3 = eidx[e + 3];
        const float4 v0 = h0[(size_t)s0 * 32 + c];
        const float4 v1 = h0[(size_t)s1 * 32 + c];
        const float4 v2 = h0[(size_t)s2 * 32 + c];
        const float4 v3 = h0[(size_t)s3 * 32 + c];
        acc.x += fmaxf(fmaf(v0.x, sc0, sh0), 0.f) + fmaxf(fmaf(v1.x, sc0, sh0), 0.f)
               + fmaxf(fmaf(v2.x, sc0, sh0), 0.f) + fmaxf(fmaf(v3.x, sc0, sh0), 0.f);
        acc.y += fmaxf(fmaf(v0.y, sc1, sh1), 0.f) + fmaxf(fmaf(v1.y, sc1, sh1), 0.f)
               + fmaxf(fmaf(v2.y, sc1, sh1), 0.f) + fmaxf(fmaf(v3.y, sc1, sh1), 0.f);
        acc.z += fmaxf(fmaf(v0.z, sc2, sh2), 0.f) + fmaxf(fmaf(v1.z, sc2, sh2), 0.f)
               + fmaxf(fmaf(v2.z, sc2, sh2), 0.f) + fmaxf(fmaf(v3.z, sc2, sh2), 0.f);
        acc.w += fmaxf(fmaf(v0.w, sc3, sh3), 0.f) + fmaxf(fmaf(v1.w, sc3, sh3), 0.f)
               + fmaxf(fmaf(v2.w, sc3, sh3), 0.f) + fmaxf(fmaf(v3.w, sc3, sh3), 0.f);
    }
    for (; e < end; e++) {
        const int s = eidx[e];
        const float4 v = h0[(size_t)s * 32 + c];
        acc.x += fmaxf(fmaf(v.x, sc0, sh0), 0.f);
        acc.y += fmaxf(fmaf(v.y, sc1, sh1), 0.f);
        acc.z += fmaxf(fmaf(v.z, sc2, sh2), 0.f);
        acc.w += fmaxf(fmaf(v.w, sc3, sh3), 0.f);
    }
    agg[(size_t)node * 32 + c] = acc;
}

// =============================================================================
// Tiled fp32x2 GEMM (round-5 proven shape): C = A@W1^T (+ B@W2^T) + bias.
// BM=64, BN=128, BK=16, 256 threads. Optional fused BN stats.
// Optional bnA: apply y = relu(bn(A)) transform while staging A (mat 0 only).
// =============================================================================
__global__ __launch_bounds__(256) void gemm_kernel(
    const float* __restrict__ A, const float* __restrict__ W1,
    const float* __restrict__ B, const float* __restrict__ W2,
    const float* __restrict__ bias, float* __restrict__ C,
    float* __restrict__ stats, const float* __restrict__ bnA,
    int Nn, int K) {

    __shared__ alignas(16) ull As2[16 * 66];   // [k][m] dup pairs, stride 66
    __shared__ alignas(16) float Ws[16][128];
    __shared__ float sh_sum[128];
    __shared__ float sh_sq[128];
    __shared__ float sbn[256];

    const int tid  = threadIdx.x;
    const int row0 = blockIdx.x * 64;
    const int warp = tid >> 5;
    const int lane = tid & 31;
    const int tm   = warp * 8;   // 8 rows per thread
    const int tn   = lane * 4;   // 4 cols per thread

    if (stats && tid < 128) { sh_sum[tid] = 0.f; sh_sq[tid] = 0.f; }
    if (bnA) sbn[tid] = bnA[tid];   // scale[0:128] | shift[0:128] (K==128 case)
    __syncthreads();

    ull acc2[8][2];
#pragma unroll
    for (int i = 0; i < 8; i++) { acc2[i][0] = 0ull; acc2[i][1] = 0ull; }

    const int nmat = (B != nullptr) ? 2 : 1;
    for (int mat = 0; mat < nmat; mat++) {
        const float* Ap = mat ? B : A;
        const float* Wp = mat ? W2 : W1;
        for (int k0 = 0; k0 < K; k0 += 16) {
            // A tile: 64 rows x 16 k, stored duplicated (a,a)
            {
                const int m  = tid >> 2;
                const int kq = (tid & 3) * 4;
                const int r  = row0 + m;
                float4 v = make_float4(0.f, 0.f, 0.f, 0.f);
                if (r < Nn) v = *(const float4*)(Ap + (size_t)r * K + k0 + kq);
                if (bnA && mat == 0) {
                    const int cc = k0 + kq;
                    v.x = fmaxf(fmaf(v.x, sbn[cc + 0], sbn[128 + cc + 0]), 0.f);
                    v.y = fmaxf(fmaf(v.y, sbn[cc + 1], sbn[128 + cc + 1]), 0.f);
                    v.z = fmaxf(fmaf(v.z, sbn[cc + 2], sbn[128 + cc + 2]), 0.f);
                    v.w = fmaxf(fmaf(v.w, sbn[cc + 3], sbn[128 + cc + 3]), 0.f);
                }
                As2[(kq + 0) * 66 + m] = dup2(v.x);
                As2[(kq + 1) * 66 + m] = dup2(v.y);
                As2[(kq + 2) * 66 + m] = dup2(v.z);
                As2[(kq + 3) * 66 + m] = dup2(v.w);
            }
            // W tile: 128 n x 16 k -> Ws[k][n]
            {
                const int n  = tid >> 1;
                const int kq = (tid & 1) * 8;
                const float* wrow = Wp + (size_t)n * K + k0 + kq;
                float4 v0 = *(const float4*)(wrow);
                float4 v1 = *(const float4*)(wrow + 4);
                Ws[kq + 0][n] = v0.x; Ws[kq + 1][n] = v0.y;
                Ws[kq + 2][n] = v0.z; Ws[kq + 3][n] = v0.w;
                Ws[kq + 4][n] = v1.x; Ws[kq + 5][n] = v1.y;
                Ws[kq + 6][n] = v1.z; Ws[kq + 7][n] = v1.w;
            }
            __syncthreads();
#pragma unroll
            for (int kk = 0; kk < 16; kk++) {
                const ulonglong2* ap = (const ulonglong2*)&As2[kk * 66 + tm];
                const ulonglong2 a01 = ap[0];   // LDS.128 broadcast
                const ulonglong2 a23 = ap[1];
                const ulonglong2 a45 = ap[2];
                const ulonglong2 a67 = ap[3];
                W4 w;
                w.v = *(const float4*)&Ws[kk][tn];   // LDS.128
                FMA2(acc2[0][0], a01.x, w.u[0]); FMA2(acc2[0][1], a01.x, w.u[1]);
                FMA2(acc2[1][0], a01.y, w.u[0]); FMA2(acc2[1][1], a01.y, w.u[1]);
                FMA2(acc2[2][0], a23.x, w.u[0]); FMA2(acc2[2][1], a23.x, w.u[1]);
                FMA2(acc2[3][0], a23.y, w.u[0]); FMA2(acc2[3][1], a23.y, w.u[1]);
                FMA2(acc2[4][0], a45.x, w.u[0]); FMA2(acc2[4][1], a45.x, w.u[1]);
                FMA2(acc2[5][0], a45.y, w.u[0]); FMA2(acc2[5][1], a45.y, w.u[1]);
                FMA2(acc2[6][0], a67.x, w.u[0]); FMA2(acc2[6][1], a67.x, w.u[1]);
                FMA2(acc2[7][0], a67.y, w.u[0]); FMA2(acc2[7][1], a67.y, w.u[1]);
            }
            __syncthreads();
        }
    }

    // ---------------- epilogue: bias, store, fused BN stats ----------------
    const float bb0 = bias[tn], bb1 = bias[tn + 1], bb2 = bias[tn + 2], bb3 = bias[tn + 3];
    float psum[4] = {0.f, 0.f, 0.f, 0.f};
    float psq[4]  = {0.f, 0.f, 0.f, 0.f};
#pragma unroll
    for (int i = 0; i < 8; i++) {
        const int r = row0 + tm + i;
        if (r < Nn) {
            F2 p0, p1;
            p0.u = acc2[i][0];
            p1.u = acc2[i][1];
            float4 o;
            o.x = p0.f.x + bb0; o.y = p0.f.y + bb1;
            o.z = p1.f.x + bb2; o.w = p1.f.y + bb3;
            *(float4*)(C + (size_t)r * 128 + tn) = o;
            psum[0] += o.x; psum[1] += o.y; psum[2] += o.z; psum[3] += o.w;
            psq[0] += o.x * o.x; psq[1] += o.y * o.y;
            psq[2] += o.z * o.z; psq[3] += o.w * o.w;
        }
    }
    if (stats) {
#pragma unroll
        for (int j = 0; j < 4; j++) {
            atomicAdd(&sh_sum[tn + j], psum[j]);
            atomicAdd(&sh_sq[tn + j], psq[j]);
        }
        __syncthreads();
        if (tid < 128) {
            atomicAdd(&stats[tid], sh_sum[tid]);
            atomicAdd(&stats[128 + tid], sh_sq[tid]);
        }
    }
}

// ---------------- BN finalize ----------------
__global__ void finalize_kernel(const float* __restrict__ stats,
                                const float* __restrict__ gamma,
                                const float* __restrict__ beta,
                                float* __restrict__ bnp, float invN) {
    const int c = threadIdx.x;  // 128 threads
    const float mu   = stats[c] * invN;
    const float var  = stats[128 + c] * invN - mu * mu;
    const float rstd = rsqrtf(var + 1e-5f);
    const float sc   = rstd * gamma[c];
    bnp[c]       = sc;
    bnp[128 + c] = beta[c] - mu * sc;
}

// ---------------- out = relu(h1*scale + shift + r) ----------------
__global__ void final_kernel(const float4* __restrict__ h1, const float* __restrict__ bnp,
                             const float4* __restrict__ r, float4* __restrict__ out,
                             int total4) {
    const int i = blockIdx.x * blockDim.x + threadIdx.x;
    if (i >= total4) return;
    const int c = (i & 31) * 4;
    const float4 v = h1[i];
    const float4 rv = r[i];
    float4 o;
    o.x = fmaxf(fmaf(v.x, bnp[c + 0], bnp[128 + c + 0]) + rv.x, 0.f);
    o.y = fmaxf(fmaf(v.y, bnp[c + 1], bnp[128 + c + 1]) + rv.y, 0.f);
    o.z = fmaxf(fmaf(v.z, bnp[c + 2], bnp[128 + c + 2]) + rv.z, 0.f);
    o.w = fmaxf(fmaf(v.w, bnp[c + 3], bnp[128 + c + 3]) + rv.w, 0.f);
    out[i] = o;
}

// ---------------- launch ----------------
extern "C" void kernel_launch(void* const* d_in, const int* in_sizes, int n_in,
                              void* d_out, int out_size) {
    const float* x    = (const float*)d_in[0];
    const int*   ei   = (const int*)d_in[1];
    const float* Wr0  = (const float*)d_in[2];
    const float* Wn0  = (const float*)d_in[3];
    const float* b0   = (const float*)d_in[4];
    const float* g0   = (const float*)d_in[5];
    const float* be0  = (const float*)d_in[6];
    const float* Wr1  = (const float*)d_in[7];
    const float* Wn1  = (const float*)d_in[8];
    const float* b1   = (const float*)d_in[9];
    const float* g1   = (const float*)d_in[10];
    const float* be1  = (const float*)d_in[11];
    const float* Wlin = (const float*)d_in[12];
    const float* blin = (const float*)d_in[13];
    float* out = (float*)d_out;

    const int N = in_sizes[0] / CINn;
    const int E = in_sizes[1] / 2;
    const int* src = ei;
    const int* dst = ei + E;

    float *agg0, *agg1, *h0, *h1, *r, *stats, *bnp;
    int *deg, *lscan, *part, *rowptr, *cursor, *eidx;
    cudaGetSymbolAddress((void**)&agg0,   g_agg0);
    cudaGetSymbolAddress((void**)&agg1,   g_agg1);
    cudaGetSymbolAddress((void**)&h0,     g_h0);
    cudaGetSymbolAddress((void**)&h1,     g_h1);
    cudaGetSymbolAddress((void**)&r,      g_r);
    cudaGetSymbolAddress((void**)&stats,  g_stats);
    cudaGetSymbolAddress((void**)&bnp,    g_bnp);
    cudaGetSymbolAddress((void**)&deg,    g_deg);
    cudaGetSymbolAddress((void**)&lscan,  g_lscan);
    cudaGetSymbolAddress((void**)&part,   g_part);
    cudaGetSymbolAddress((void**)&rowptr, g_rowptr);
    cudaGetSymbolAddress((void**)&cursor, g_cursor);
    cudaGetSymbolAddress((void**)&eidx,   g_eidx);

    cudaMemsetAsync(deg,   0, (size_t)N * sizeof(int));
    cudaMemsetAsync(stats, 0, 4 * COUTn * sizeof(float));

    const int nb = (N + SCAN_B - 1) / SCAN_B;

    // ---- CSR build (once; reused by both layers) ----
    hist_kernel<<<(E + 255) / 256, 256>>>(dst, deg, E);
    scan1_kernel<<<nb, SCAN_B>>>(deg, lscan, part, N);
    scan2_kernel<<<1, 256>>>(part, nb);
    scan3_kernel<<<(N + 255) / 256, 256>>>(lscan, part, rowptr, cursor, N, E);
    fill_kernel<<<(E + 255) / 256, 256>>>(src, dst, cursor, eidx, E);

    const int gemmBlocks = (N + 63) / 64;
    const int T4 = N * 32;

    // ---- Layer 0 ----
    gather0_kernel<<<(N + 15) / 16, 256>>>(rowptr, eidx, (const float4*)x,
                                           (float4*)agg0, N);
    // r = x @ Wlin^T + blin
    gemm_kernel<<<gemmBlocks, 256>>>(x, Wlin, nullptr, nullptr, blin, r,
                                     nullptr, nullptr, N, CINn);
    // h0 = x @ Wr0^T + agg0 @ Wn0^T + b0 (+ fused BN stats)
    gemm_kernel<<<gemmBlocks, 256>>>(x, Wr0, agg0, Wn0, b0, h0,
                                     stats, nullptr, N, CINn);
    finalize_kernel<<<1, 128>>>(stats, g0, be0, bnp, 1.0f / (float)N);

    // ---- Layer 1 (y never materialized: bn+relu fused into both consumers) ----
    gather1_kernel<<<(N + 7) / 8, 256>>>(rowptr, eidx, (const float4*)h0, bnp,
                                         (float4*)agg1, N);
    // h1 = relu(bn(h0)) @ Wr1^T + agg1 @ Wn1^T + b1 (+ fused BN stats)
    gemm_kernel<<<gemmBlocks, 256>>>(h0, Wr1, agg1, Wn1, b1, h1,
                                     stats + 2 * COUTn, bnp, N, COUTn);
    finalize_kernel<<<1, 128>>>(stats + 2 * COUTn, g1, be1, bnp + 2 * COUTn, 1.0f / (float)N);
    final_kernel<<<(T4 + 255) / 256, 256>>>((const float4*)h1, bnp + 2 * COUTn,
                                            (const float4*)r, (float4*)out, T4);
}

// round 8
// speedup vs baseline: 1.0700x; 1.0199x over previous
#include <cuda_runtime.h>
#include <cstdint>

typedef unsigned long long ull;

// Problem constants (fixed shapes per reference)
#define NN    100000
#define EE    1600000
#define CINn  64
#define COUTn 128
#define SCAN_B 512

// ---------------- scratch (static device globals; no runtime alloc) ----------------
__device__ float g_agg0[(size_t)NN * CINn];
__device__ float g_agg1[(size_t)NN * COUTn];
__device__ float g_h0[(size_t)NN * COUTn];
__device__ float g_h1[(size_t)NN * COUTn];
__device__ float g_r[(size_t)NN * COUTn];
__device__ float g_stats[4 * COUTn];
__device__ float g_bnp[4 * COUTn];
// CSR scratch
__device__ int g_deg[NN];
__device__ int g_lscan[NN];
__device__ int g_part[256];
__device__ int g_rowptr[NN + 1];
__device__ int g_cursor[NN];
__device__ int g_eidx[EE];

// ---------------- packed fp32x2 FMA ----------------
#define FMA2(acc, a, w) \
    asm("fma.rn.f32x2 %0, %1, %2, %0;" : "+l"(acc) : "l"(a), "l"(w))

__device__ __forceinline__ ull dup2(float f) {
    ull r;
    asm("mov.b64 %0, {%1, %1};" : "=l"(r) : "f"(f));
    return r;
}

union F2 { ull u; float2 f; };
union W4 { float4 v; ull u[2]; };

// =============================================================================
// CSR build: histogram -> scan -> fill
// =============================================================================
__global__ void hist_kernel(const int* __restrict__ dst, int* __restrict__ deg, int E) {
    const int e = blockIdx.x * blockDim.x + threadIdx.x;
    if (e < E) atomicAdd(&deg[dst[e]], 1);
}

__global__ void scan1_kernel(const int* __restrict__ deg, int* __restrict__ lscan,
                             int* __restrict__ part, int N) {
    __shared__ int sh[SCAN_B];
    const int i = blockIdx.x * SCAN_B + threadIdx.x;
    const int v = (i < N) ? deg[i] : 0;
    sh[threadIdx.x] = v;
    __syncthreads();
#pragma unroll
    for (int off = 1; off < SCAN_B; off <<= 1) {
        int t = (threadIdx.x >= off) ? sh[threadIdx.x - off] : 0;
        __syncthreads();
        sh[threadIdx.x] += t;
        __syncthreads();
    }
    if (i < N) lscan[i] = sh[threadIdx.x] - v;
    if (threadIdx.x == SCAN_B - 1) part[blockIdx.x] = sh[threadIdx.x];
}

__global__ void scan2_kernel(int* __restrict__ part, int nb) {
    __shared__ int sh[256];
    const int v = (threadIdx.x < nb) ? part[threadIdx.x] : 0;
    sh[threadIdx.x] = v;
    __syncthreads();
#pragma unroll
    for (int off = 1; off < 256; off <<= 1) {
        int t = (threadIdx.x >= off) ? sh[threadIdx.x - off] : 0;
        __syncthreads();
        sh[threadIdx.x] += t;
        __syncthreads();
    }
    if (threadIdx.x < nb) part[threadIdx.x] = sh[threadIdx.x] - v;
}

__global__ void scan3_kernel(const int* __restrict__ lscan, const int* __restrict__ part,
                             int* __restrict__ rowptr, int* __restrict__ cursor,
                             int N, int E) {
    const int i = blockIdx.x * blockDim.x + threadIdx.x;
    if (i < N) {
        const int r = lscan[i] + part[i / SCAN_B];
        rowptr[i] = r;
        cursor[i] = r;
    }
    if (i == 0) rowptr[N] = E;
}

__global__ void fill_kernel(const int* __restrict__ src, const int* __restrict__ dst,
                            int* __restrict__ cursor, int* __restrict__ eidx, int E) {
    const int e = blockIdx.x * blockDim.x + threadIdx.x;
    if (e < E) {
        const int pos = atomicAdd(&cursor[dst[e]], 1);
        eidx[pos] = src[e];
    }
}

// =============================================================================
// Gather (layer 0): agg0[n] = sum x[src], 4-edge unrolled, C4=16
// =============================================================================
__global__ void gather0_kernel(const int* __restrict__ rowptr, const int* __restrict__ eidx,
                               const float4* __restrict__ feat, float4* __restrict__ agg,
                               int N) {
    const int g = threadIdx.x >> 4;
    const int c = threadIdx.x & 15;
    const int node = blockIdx.x * 16 + g;
    if (node >= N) return;
    const int beg = rowptr[node];
    const int end = rowptr[node + 1];
    float4 acc = make_float4(0.f, 0.f, 0.f, 0.f);
    int e = beg;
    for (; e + 3 < end; e += 4) {
        const int s0 = eidx[e], s1 = eidx[e + 1], s2 = eidx[e + 2], s3 = eidx[e + 3];
        const float4 v0 = feat[(size_t)s0 * 16 + c];
        const float4 v1 = feat[(size_t)s1 * 16 + c];
        const float4 v2 = feat[(size_t)s2 * 16 + c];
        const float4 v3 = feat[(size_t)s3 * 16 + c];
        acc.x += v0.x + v1.x + v2.x + v3.x;
        acc.y += v0.y + v1.y + v2.y + v3.y;
        acc.z += v0.z + v1.z + v2.z + v3.z;
        acc.w += v0.w + v1.w + v2.w + v3.w;
    }
    for (; e < end; e++) {
        const int s = eidx[e];
        const float4 v = feat[(size_t)s * 16 + c];
        acc.x += v.x; acc.y += v.y; acc.z += v.z; acc.w += v.w;
    }
    agg[(size_t)node * 16 + c] = acc;
}

// =============================================================================
// Gather (layer 1) with fused bn+relu: agg1[n] = sum relu(bn(h0[src])), C4=32
// =============================================================================
__global__ void gather1_kernel(const int* __restrict__ rowptr, const int* __restrict__ eidx,
                               const float4* __restrict__ h0, const float* __restrict__ bnp,
                               float4* __restrict__ agg, int N) {
    const int g = threadIdx.x >> 5;
    const int c = threadIdx.x & 31;
    const int node = blockIdx.x * 8 + g;
    if (node >= N) return;
    const float sc0 = bnp[c * 4 + 0], sh0 = bnp[128 + c * 4 + 0];
    const float sc1 = bnp[c * 4 + 1], sh1 = bnp[128 + c * 4 + 1];
    const float sc2 = bnp[c * 4 + 2], sh2 = bnp[128 + c * 4 + 2];
    const float sc3 = bnp[c * 4 + 3], sh3 = bnp[128 + c * 4 + 3];
    const int beg = rowptr[node];
    const int end = rowptr[node + 1];
    float4 acc = make_float4(0.f, 0.f, 0.f, 0.f);
    int e = beg;
    for (; e + 3 < end; e += 4) {
        const int s0 = eidx[e], s1 = eidx[e + 1], s2 = eidx[e + 2], s3 = eidx[e + 3];
        const float4 v0 = h0[(size_t)s0 * 32 + c];
        const float4 v1 = h0[(size_t)s1 * 32 + c];
        const float4 v2 = h0[(size_t)s2 * 32 + c];
        const float4 v3 = h0[(size_t)s3 * 32 + c];
        acc.x += fmaxf(fmaf(v0.x, sc0, sh0), 0.f) + fmaxf(fmaf(v1.x, sc0, sh0), 0.f)
               + fmaxf(fmaf(v2.x, sc0, sh0), 0.f) + fmaxf(fmaf(v3.x, sc0, sh0), 0.f);
        acc.y += fmaxf(fmaf(v0.y, sc1, sh1), 0.f) + fmaxf(fmaf(v1.y, sc1, sh1), 0.f)
               + fmaxf(fmaf(v2.y, sc1, sh1), 0.f) + fmaxf(fmaf(v3.y, sc1, sh1), 0.f);
        acc.z += fmaxf(fmaf(v0.z, sc2, sh2), 0.f) + fmaxf(fmaf(v1.z, sc2, sh2), 0.f)
               + fmaxf(fmaf(v2.z, sc2, sh2), 0.f) + fmaxf(fmaf(v3.z, sc2, sh2), 0.f);
        acc.w += fmaxf(fmaf(v0.w, sc3, sh3), 0.f) + fmaxf(fmaf(v1.w, sc3, sh3), 0.f)
               + fmaxf(fmaf(v2.w, sc3, sh3), 0.f) + fmaxf(fmaf(v3.w, sc3, sh3), 0.f);
    }
    for (; e < end; e++) {
        const int s = eidx[e];
        const float4 v = h0[(size_t)s * 32 + c];
        acc.x += fmaxf(fmaf(v.x, sc0, sh0), 0.f);
        acc.y += fmaxf(fmaf(v.y, sc1, sh1), 0.f);
        acc.z += fmaxf(fmaf(v.z, sc2, sh2), 0.f);
        acc.w += fmaxf(fmaf(v.w, sc3, sh3), 0.f);
    }
    agg[(size_t)node * 32 + c] = acc;
}

// =============================================================================
// Tiled fp32x2 GEMM: C = A@W1^T (+ B@W2^T) [+ C if accumC] + bias(if set).
// BM=64, BN=128, BK=16, 256 threads. Optional fused BN stats; optional bnA
// (apply relu(bn(A)) while staging A, mat 0 only).
// =============================================================================
__global__ __launch_bounds__(256) void gemm_kernel(
    const float* __restrict__ A, const float* __restrict__ W1,
    const float* __restrict__ B, const float* __restrict__ W2,
    const float* __restrict__ bias, float* __restrict__ C,
    float* __restrict__ stats, const float* __restrict__ bnA,
    int Nn, int K, int accumC) {

    __shared__ alignas(16) ull As2[16 * 66];   // [k][m] dup pairs, stride 66
    __shared__ alignas(16) float Ws[16][128];
    __shared__ float sh_sum[128];
    __shared__ float sh_sq[128];
    __shared__ float sbn[256];

    const int tid  = threadIdx.x;
    const int row0 = blockIdx.x * 64;
    const int warp = tid >> 5;
    const int lane = tid & 31;
    const int tm   = warp * 8;   // 8 rows per thread
    const int tn   = lane * 4;   // 4 cols per thread

    if (stats && tid < 128) { sh_sum[tid] = 0.f; sh_sq[tid] = 0.f; }
    if (bnA) sbn[tid] = bnA[tid];   // scale[0:128] | shift[0:128] (K==128 case)
    __syncthreads();

    ull acc2[8][2];
#pragma unroll
    for (int i = 0; i < 8; i++) { acc2[i][0] = 0ull; acc2[i][1] = 0ull; }

    const int nmat = (B != nullptr) ? 2 : 1;
    for (int mat = 0; mat < nmat; mat++) {
        const float* Ap = mat ? B : A;
        const float* Wp = mat ? W2 : W1;
        for (int k0 = 0; k0 < K; k0 += 16) {
            // A tile: 64 rows x 16 k, stored duplicated (a,a)
            {
                const int m  = tid >> 2;
                const int kq = (tid & 3) * 4;
                const int r  = row0 + m;
                float4 v = make_float4(0.f, 0.f, 0.f, 0.f);
                if (r < Nn) v = *(const float4*)(Ap + (size_t)r * K + k0 + kq);
                if (bnA && mat == 0) {
                    const int cc = k0 + kq;
                    v.x = fmaxf(fmaf(v.x, sbn[cc + 0], sbn[128 + cc + 0]), 0.f);
                    v.y = fmaxf(fmaf(v.y, sbn[cc + 1], sbn[128 + cc + 1]), 0.f);
                    v.z = fmaxf(fmaf(v.z, sbn[cc + 2], sbn[128 + cc + 2]), 0.f);
                    v.w = fmaxf(fmaf(v.w, sbn[cc + 3], sbn[128 + cc + 3]), 0.f);
                }
                As2[(kq + 0) * 66 + m] = dup2(v.x);
                As2[(kq + 1) * 66 + m] = dup2(v.y);
                As2[(kq + 2) * 66 + m] = dup2(v.z);
                As2[(kq + 3) * 66 + m] = dup2(v.w);
            }
            // W tile: 128 n x 16 k -> Ws[k][n]
            {
                const int n  = tid >> 1;
                const int kq = (tid & 1) * 8;
                const float* wrow = Wp + (size_t)n * K + k0 + kq;
                float4 v0 = *(const float4*)(wrow);
                float4 v1 = *(const float4*)(wrow + 4);
                Ws[kq + 0][n] = v0.x; Ws[kq + 1][n] = v0.y;
                Ws[kq + 2][n] = v0.z; Ws[kq + 3][n] = v0.w;
                Ws[kq + 4][n] = v1.x; Ws[kq + 5][n] = v1.y;
                Ws[kq + 6][n] = v1.z; Ws[kq + 7][n] = v1.w;
            }
            __syncthreads();
#pragma unroll
            for (int kk = 0; kk < 16; kk++) {
                const ulonglong2* ap = (const ulonglong2*)&As2[kk * 66 + tm];
                const ulonglong2 a01 = ap[0];   // LDS.128 broadcast
                const ulonglong2 a23 = ap[1];
                const ulonglong2 a45 = ap[2];
                const ulonglong2 a67 = ap[3];
                W4 w;
                w.v = *(const float4*)&Ws[kk][tn];   // LDS.128
                FMA2(acc2[0][0], a01.x, w.u[0]); FMA2(acc2[0][1], a01.x, w.u[1]);
                FMA2(acc2[1][0], a01.y, w.u[0]); FMA2(acc2[1][1], a01.y, w.u[1]);
                FMA2(acc2[2][0], a23.x, w.u[0]); FMA2(acc2[2][1], a23.x, w.u[1]);
                FMA2(acc2[3][0], a23.y, w.u[0]); FMA2(acc2[3][1], a23.y, w.u[1]);
                FMA2(acc2[4][0], a45.x, w.u[0]); FMA2(acc2[4][1], a45.x, w.u[1]);
                FMA2(acc2[5][0], a45.y, w.u[0]); FMA2(acc2[5][1], a45.y, w.u[1]);
                FMA2(acc2[6][0], a67.x, w.u[0]); FMA2(acc2[6][1], a67.x, w.u[1]);
                FMA2(acc2[7][0], a67.y, w.u[0]); FMA2(acc2[7][1], a67.y, w.u[1]);
            }
            __syncthreads();
        }
    }

    // ---------------- epilogue: (accum), bias, store, fused BN stats ----------------
    const float bb0 = bias ? bias[tn]     : 0.f;
    const float bb1 = bias ? bias[tn + 1] : 0.f;
    const float bb2 = bias ? bias[tn + 2] : 0.f;
    const float bb3 = bias ? bias[tn + 3] : 0.f;
    float psum[4] = {0.f, 0.f, 0.f, 0.f};
    float psq[4]  = {0.f, 0.f, 0.f, 0.f};
#pragma unroll
    for (int i = 0; i < 8; i++) {
        const int r = row0 + tm + i;
        if (r < Nn) {
            F2 p0, p1;
            p0.u = acc2[i][0];
            p1.u = acc2[i][1];
            float4 o;
            o.x = p0.f.x + bb0; o.y = p0.f.y + bb1;
            o.z = p1.f.x + bb2; o.w = p1.f.y + bb3;
            if (accumC) {
                const float4 prev = *(const float4*)(C + (size_t)r * 128 + tn);
                o.x += prev.x; o.y += prev.y; o.z += prev.z; o.w += prev.w;
            }
            *(float4*)(C + (size_t)r * 128 + tn) = o;
            psum[0] += o.x; psum[1] += o.y; psum[2] += o.z; psum[3] += o.w;
            psq[0] += o.x * o.x; psq[1] += o.y * o.y;
            psq[2] += o.z * o.z; psq[3] += o.w * o.w;
        }
    }
    if (stats) {
#pragma unroll
        for (int j = 0; j < 4; j++) {
            atomicAdd(&sh_sum[tn + j], psum[j]);
            atomicAdd(&sh_sq[tn + j], psq[j]);
        }
        __syncthreads();
        if (tid < 128) {
            atomicAdd(&stats[tid], sh_sum[tid]);
            atomicAdd(&stats[128 + tid], sh_sq[tid]);
        }
    }
}

// ---------------- BN finalize ----------------
__global__ void finalize_kernel(const float* __restrict__ stats,
                                const float* __restrict__ gamma,
                                const float* __restrict__ beta,
                                float* __restrict__ bnp, float invN) {
    const int c = threadIdx.x;  // 128 threads
    const float mu   = stats[c] * invN;
    const float var  = stats[128 + c] * invN - mu * mu;
    const float rstd = rsqrtf(var + 1e-5f);
    const float sc   = rstd * gamma[c];
    bnp[c]       = sc;
    bnp[128 + c] = beta[c] - mu * sc;
}

// ---------------- out = relu(h1*scale + shift + r) ----------------
__global__ void final_kernel(const float4* __restrict__ h1, const float* __restrict__ bnp,
                             const float4* __restrict__ r, float4* __restrict__ out,
                             int total4) {
    const int i = blockIdx.x * blockDim.x + threadIdx.x;
    if (i >= total4) return;
    const int c = (i & 31) * 4;
    const float4 v = h1[i];
    const float4 rv = r[i];
    float4 o;
    o.x = fmaxf(fmaf(v.x, bnp[c + 0], bnp[128 + c + 0]) + rv.x, 0.f);
    o.y = fmaxf(fmaf(v.y, bnp[c + 1], bnp[128 + c + 1]) + rv.y, 0.f);
    o.z = fmaxf(fmaf(v.z, bnp[c + 2], bnp[128 + c + 2]) + rv.z, 0.f);
    o.w = fmaxf(fmaf(v.w, bnp[c + 3], bnp[128 + c + 3]) + rv.w, 0.f);
    out[i] = o;
}

// ---------------- launch ----------------
extern "C" void kernel_launch(void* const* d_in, const int* in_sizes, int n_in,
                              void* d_out, int out_size) {
    const float* x    = (const float*)d_in[0];
    const int*   ei   = (const int*)d_in[1];
    const float* Wr0  = (const float*)d_in[2];
    const float* Wn0  = (const float*)d_in[3];
    const float* b0   = (const float*)d_in[4];
    const float* g0   = (const float*)d_in[5];
    const float* be0  = (const float*)d_in[6];
    const float* Wr1  = (const float*)d_in[7];
    const float* Wn1  = (const float*)d_in[8];
    const float* b1   = (const float*)d_in[9];
    const float* g1   = (const float*)d_in[10];
    const float* be1  = (const float*)d_in[11];
    const float* Wlin = (const float*)d_in[12];
    const float* blin = (const float*)d_in[13];
    float* out = (float*)d_out;

    const int N = in_sizes[0] / CINn;
    const int E = in_sizes[1] / 2;
    const int* src = ei;
    const int* dst = ei + E;

    float *agg0, *agg1, *h0, *h1, *r, *stats, *bnp;
    int *deg, *lscan, *part, *rowptr, *cursor, *eidx;
    cudaGetSymbolAddress((void**)&agg0,   g_agg0);
    cudaGetSymbolAddress((void**)&agg1,   g_agg1);
    cudaGetSymbolAddress((void**)&h0,     g_h0);
    cudaGetSymbolAddress((void**)&h1,     g_h1);
    cudaGetSymbolAddress((void**)&r,      g_r);
    cudaGetSymbolAddress((void**)&stats,  g_stats);
    cudaGetSymbolAddress((void**)&bnp,    g_bnp);
    cudaGetSymbolAddress((void**)&deg,    g_deg);
    cudaGetSymbolAddress((void**)&lscan,  g_lscan);
    cudaGetSymbolAddress((void**)&part,   g_part);
    cudaGetSymbolAddress((void**)&rowptr, g_rowptr);
    cudaGetSymbolAddress((void**)&cursor, g_cursor);
    cudaGetSymbolAddress((void**)&eidx,   g_eidx);

    // side stream + fork/join events (created once; graph-capture safe: the
    // fork is expressed via event record/wait which capture turns into edges)
    static cudaStream_t s2 = nullptr;
    static cudaEvent_t ev0 = nullptr, ev1 = nullptr, ev2 = nullptr, ev3 = nullptr;
    if (!s2) {
        cudaStreamCreate(&s2);
        cudaEventCreateWithFlags(&ev0, cudaEventDisableTiming);
        cudaEventCreateWithFlags(&ev1, cudaEventDisableTiming);
        cudaEventCreateWithFlags(&ev2, cudaEventDisableTiming);
        cudaEventCreateWithFlags(&ev3, cudaEventDisableTiming);
    }

    cudaMemsetAsync(deg,   0, (size_t)N * sizeof(int));
    cudaMemsetAsync(stats, 0, 4 * COUTn * sizeof(float));

    const int nb = (N + SCAN_B - 1) / SCAN_B;
    const int gemmBlocks = (N + 63) / 64;
    const int T4 = N * 32;

    // ---- fork: r = x @ Wlin^T + blin on side stream (independent of graph) ----
    cudaEventRecord(ev0, 0);
    cudaStreamWaitEvent(s2, ev0, 0);
    gemm_kernel<<<gemmBlocks, 256, 0, s2>>>(x, Wlin, nullptr, nullptr, blin, r,
                                            nullptr, nullptr, N, CINn, 0);
    cudaEventRecord(ev1, s2);

    // ---- main: CSR build + layer-0 aggregation ----
    hist_kernel<<<(E + 255) / 256, 256>>>(dst, deg, E);
    scan1_kernel<<<nb, SCAN_B>>>(deg, lscan, part, N);
    scan2_kernel<<<1, 256>>>(part, nb);
    scan3_kernel<<<(N + 255) / 256, 256>>>(lscan, part, rowptr, cursor, N, E);
    fill_kernel<<<(E + 255) / 256, 256>>>(src, dst, cursor, eidx, E);
    gather0_kernel<<<(N + 15) / 16, 256>>>(rowptr, eidx, (const float4*)x,
                                           (float4*)agg0, N);

    // h0 = x @ Wr0^T + agg0 @ Wn0^T + b0 (+ fused BN stats)
    gemm_kernel<<<gemmBlocks, 256>>>(x, Wr0, agg0, Wn0, b0, h0,
                                     stats, nullptr, N, CINn, 0);
    finalize_kernel<<<1, 128>>>(stats, g0, be0, bnp, 1.0f / (float)N);

    // ---- fork: gather1 (needs h0, bnp) on side stream ----
    cudaEventRecord(ev2, 0);
    cudaStreamWaitEvent(s2, ev2, 0);
    gather1_kernel<<<(N + 7) / 8, 256, 0, s2>>>(rowptr, eidx, (const float4*)h0, bnp,
                                                (float4*)agg1, N);
    cudaEventRecord(ev3, s2);

    // ---- main (concurrent with gather1): h1 = relu(bn(h0)) @ Wr1^T + b1 ----
    gemm_kernel<<<gemmBlocks, 256>>>(h0, Wr1, nullptr, nullptr, b1, h1,
                                     nullptr, bnp, N, COUTn, 0);

    // ---- join, then h1 += agg1 @ Wn1^T (+ fused BN stats over final h1) ----
    cudaStreamWaitEvent(0, ev3, 0);
    gemm_kernel<<<gemmBlocks, 256>>>(agg1, Wn1, nullptr, nullptr, nullptr, h1,
                                     stats + 2 * COUTn, nullptr, N, COUTn, 1);
    finalize_kernel<<<1, 128>>>(stats + 2 * COUTn, g1, be1, bnp + 2 * COUTn, 1.0f / (float)N);

    // ---- join r, then out = relu(bn(h1) + r) ----
    cudaStreamWaitEvent(0, ev1, 0);
    final_kernel<<<(T4 + 255) / 256, 256>>>((const float4*)h1, bnp + 2 * COUTn,
                                            (const float4*)r, (float4*)out, T4);
}